// round 12
// baseline (speedup 1.0000x reference)
#include <cuda_runtime.h>
#include <cuda_fp16.h>

#define GRID 148
#define NTHR 512
#define Bsz 64
#define Ssz 1024
#define Tsz 300
#define Hsz 512
#define Vsz 5000
#define KQn 256

typedef unsigned long long ull;

// ---------------- device scratch ----------------
__device__ __half g_k[Bsz * Ssz * KQn];   // fp16 keys   (32 MB)
__device__ __half g_v[Bsz * Ssz * Hsz];   // fp16 values (64 MB)
__device__ float g_h1[2][Bsz * Hsz];
__device__ float g_c1[Bsz * Hsz];
__device__ float g_h2[2][Bsz * Hsz];
__device__ float g_c2[Bsz * Hsz];
__device__ float g_ctx[Bsz * Hsz];
__device__ float g_cdn[Bsz * Hsz];
__device__ float g_g1p[8 * Bsz * 2048];
__device__ float g_g2p[6 * Bsz * 2048];
__device__ float g_cdp[5 * Bsz * 512];
__device__ float g_lgp[3][Bsz * 5120];
__device__ volatile int g_flags[GRID];
__device__ volatile int g_genv;

// ---------------- shared arena ----------------
struct __align__(16) Sh {
    union {
        struct { float As[64][36]; float Bs[128][36]; } g;
        struct { float h2s[512]; float qs[256]; float sc[1024];
                 float red[16]; float part[8][528]; } a;
    } u;
    int toks[64];
};

// ---------------- grid barrier ----------------
__device__ __forceinline__ void gsync(int& gs) {
    gs++;
    __syncthreads();
    if (blockIdx.x == 0) {
        if (threadIdx.x > 0 && threadIdx.x < GRID)
            while (g_flags[threadIdx.x] < gs) __nanosleep(32);
        __syncthreads();
        if (threadIdx.x == 0) { __threadfence(); g_genv = gs; }
    } else if (threadIdx.x == 0) {
        __threadfence();
        g_flags[blockIdx.x] = gs;
        while (g_genv < gs) __nanosleep(32);
    }
    __syncthreads();
    __threadfence();
}

__device__ __forceinline__ float sigf(float x) { return 1.f / (1.f + __expf(-x)); }

__device__ __forceinline__ void fma2(ull& d, ull a, ull b) {
    asm("fma.rn.f32x2 %0, %1, %2, %3;" : "=l"(d) : "l"(a), "l"(b), "l"(d));
}
__device__ __forceinline__ float pairsum(ull x) {
    float lo, hi;
    asm("mov.b64 {%0, %1}, %2;" : "=f"(lo), "=f"(hi) : "l"(x));
    return lo + hi;
}
__device__ __forceinline__ float2 h2f(unsigned p) {
    __half2 h = *reinterpret_cast<__half2*>(&p);
    return __half22float2(h);
}

// ---------------- 64M x 128N GEMM tile, f32x2, 8m x 2n warp tiling ---------
// out[m][n] = sum_k A[m][k] * B[n][k]
// AM 0: A row-major stride arow. AM 1: [emb[tok]|A1|A2] each 512.
// AM 2: [A0(512)|A1(512+)]. B row n: k<segB -> B0(len L0) else B1(len L1).
// OB 1: output cast to fp16.
template <int AM, int OB>
__device__ __forceinline__ void gemm2(
    const float* __restrict__ A0, const float* __restrict__ A1,
    const float* __restrict__ A2, long arow,
    const float* __restrict__ B0, long L0, int segB,
    const float* __restrict__ B1, long L1,
    int nbase, int Nmax, int kbeg, int kend,
    void* __restrict__ outp, long OS, const float* __restrict__ bias,
    const int* __restrict__ yy, int t, Sh& sh)
{
    const int tid = threadIdx.x;
    const int nt = tid & 31;
    const int w = tid >> 5;
    const int mw = (w & 7) * 8;          // warp m base (8 rows)
    const int nh = (w >> 3) * 64;        // warp n half (64 cols)
    const int ar = tid >> 3;             // fill row 0..63
    const int kq4 = (tid & 7) * 4;       // fill k col

    if (AM == 1) {
        if (tid < 64) sh.toks[tid] = (t == 0) ? 0 : yy[tid * Tsz + (t - 1)];
        __syncthreads();
    }

    ull acc[8][2];
#pragma unroll
    for (int i = 0; i < 8; i++) { acc[i][0] = 0ULL; acc[i][1] = 0ULL; }

    float4 pa, pb0, pb1;
    auto loadA = [&](int kb, float4& d) {
        int k = kb + kq4;
        const float* rp;
        if (AM == 0)      rp = A0 + (long)ar * arow + k;
        else if (AM == 1) rp = (k < 512)  ? A0 + (long)sh.toks[ar] * 512 + k
                         : (k < 1024) ? A1 + ar * 512 + (k - 512)
                                      : A2 + ar * 512 + (k - 1024);
        else              rp = (k < 512) ? A0 + ar * 512 + k
                                         : A1 + ar * 512 + (k - 512);
        d = *(const float4*)rp;
    };
    auto loadB = [&](int kb, int n, float4& d) {
        int ng = nbase + n;
        int k = kb + kq4;
        d = make_float4(0.f, 0.f, 0.f, 0.f);
        if (ng < Nmax) {
            const float* rp = (k < segB) ? B0 + (long)ng * L0 + k
                                         : B1 + (long)ng * L1 + (k - segB);
            d = *(const float4*)rp;
        }
    };

    loadA(kbeg, pa);
    loadB(kbeg, ar, pb0);
    loadB(kbeg, ar + 64, pb1);

    for (int kb = kbeg; kb < kend; kb += 32) {
        __syncthreads();
        *(float4*)&sh.u.g.As[ar][kq4]      = pa;
        *(float4*)&sh.u.g.Bs[ar][kq4]      = pb0;
        *(float4*)&sh.u.g.Bs[ar + 64][kq4] = pb1;
        __syncthreads();
        if (kb + 32 < kend) {
            loadA(kb + 32, pa);
            loadB(kb + 32, ar, pb0);
            loadB(kb + 32, ar + 64, pb1);
        }
#pragma unroll
        for (int kq = 0; kq < 8; kq++) {
            ulonglong2 b0 = *(const ulonglong2*)&sh.u.g.Bs[nh + nt][4 * kq];
            ulonglong2 b1 = *(const ulonglong2*)&sh.u.g.Bs[nh + nt + 32][4 * kq];
#pragma unroll
            for (int i = 0; i < 8; i++) {
                ulonglong2 a = *(const ulonglong2*)&sh.u.g.As[mw + i][4 * kq];
                fma2(acc[i][0], a.x, b0.x);
                fma2(acc[i][0], a.y, b0.y);
                fma2(acc[i][1], a.x, b1.x);
                fma2(acc[i][1], a.y, b1.y);
            }
        }
    }
    __syncthreads();

#pragma unroll
    for (int i = 0; i < 8; i++) {
        long m = mw + i;
#pragma unroll
        for (int j = 0; j < 2; j++) {
            int n = nbase + nh + nt + 32 * j;
            if (n < Nmax) {
                float s = pairsum(acc[i][j]);
                if (bias) s += bias[n];
                if (OB) ((__half*)outp)[m * OS + n] = __float2half(s);
                else    ((float*)outp)[m * OS + n] = s;
            }
        }
    }
    __syncthreads();
}

// logits split-K geometry: 3 chunks {192,192,128} over k=512
__device__ __forceinline__ void lg_geom(int ks, int& kb, int& kl) {
    kb = ks * 192;
    kl = (ks < 2) ? 192 : 128;
}
// LSTM2 split-K geometry: 6 chunks {192,192,160,160,160,160} over k=1024
__device__ __forceinline__ void l2_geom(int ks, int& kb, int& kl) {
    if (ks < 2) { kb = ks * 192; kl = 192; }
    else        { kb = 384 + (ks - 2) * 160; kl = 160; }
}

// ---------------- persistent mega-kernel ----------------
__global__ void __launch_bounds__(NTHR, 1)
mega(const float* __restrict__ enc, const int* __restrict__ y,
     const float* __restrict__ emb,
     const float* __restrict__ Wq, const float* __restrict__ bq,
     const float* __restrict__ Wk, const float* __restrict__ bk,
     const float* __restrict__ Wv, const float* __restrict__ bv,
     const float* __restrict__ Wih1, const float* __restrict__ bih1,
     const float* __restrict__ Whh1, const float* __restrict__ bhh1,
     const float* __restrict__ Wih2, const float* __restrict__ bih2,
     const float* __restrict__ Whh2, const float* __restrict__ bhh2,
     const float* __restrict__ Wcdn, const float* __restrict__ bcdn,
     const float* __restrict__ bcls, float* __restrict__ out)
{
    __shared__ Sh sh;
    const int tid = threadIdx.x;
    const int bx = blockIdx.x;
    int gs = g_genv;

    // ---- init: zero recurrent state ----
    for (int i = bx * NTHR + tid; i < 5 * Bsz * Hsz; i += GRID * NTHR) {
        int a = i >> 15, j = i & 32767;
        float* p = a == 0 ? g_h1[0] : a == 1 ? g_c1 : a == 2 ? g_h2[0]
                 : a == 3 ? g_c2 : g_ctx;
        p[j] = 0.f;
    }
    // ---- kv projection (fp16 output) ----
    for (int j = bx; j < 6144; j += GRID) {
        if (j < 2048) {
            int mt_ = j >> 1, nt_ = j & 1;
            gemm2<0, 1>(enc + (long)mt_ * 64 * 512, nullptr, nullptr, 512,
                        Wk, 512, 1 << 30, nullptr, 0,
                        nt_ * 128, 1 << 30, 0, 512,
                        g_k + (long)mt_ * 64 * KQn, KQn, bk, nullptr, 0, sh);
        } else {
            int v = j - 2048;
            int mt_ = v >> 2, nt_ = v & 3;
            gemm2<0, 1>(enc + (long)mt_ * 64 * 512, nullptr, nullptr, 512,
                        Wv, 512, 1 << 30, nullptr, 0,
                        nt_ * 128, 1 << 30, 0, 512,
                        g_v + (long)mt_ * 64 * Hsz, Hsz, bv, nullptr, 0, sh);
        }
    }
    gsync(gs);

    for (int t = 0; t < Tsz; t++) {
        const float* h1o = g_h1[t & 1];
        float*       h1n = g_h1[(t + 1) & 1];
        const float* h2o = g_h2[t & 1];
        float*       h2n = g_h2[(t + 1) & 1];

        // ---- P1: LSTM1 (blk 0-127: 16nt x 8sk, k=192) || cdn(t-1) (128-147) ----
        if (bx < 128) {
            int ntile = bx >> 3, ks = bx & 7;
            gemm2<1, 0>(emb, g_ctx, h1o, 0,
                        Wih1, 1024, 1024, Whh1, 512,
                        ntile * 128, 1 << 30, ks * 192, ks * 192 + 192,
                        g_g1p + (long)ks * 131072, 2048, nullptr, y, t, sh);
        } else if (t > 0) {
            int u = bx - 128, ntile = u / 5, ks = u % 5;
            int kb = ks < 2 ? ks * 224 : 448 + (ks - 2) * 192;
            int kl = ks < 2 ? 224 : 192;
            gemm2<2, 0>(h2o, g_ctx, nullptr, 0,
                        Wcdn, 1024, 1 << 30, nullptr, 0,
                        ntile * 128, 1 << 30, kb, kb + kl,
                        g_cdp + (long)ks * 32768, 512, nullptr, nullptr, 0, sh);
        }
        gsync(gs);

        // ---- P2: cell1 + cdn-red(t-1) + logits-red(t-2) ----
        {
            int gid = bx * NTHR + tid;
            if (gid < 32768) {
                int b = gid >> 9, u = gid & 511;
                float gt[4];
#pragma unroll
                for (int g = 0; g < 4; g++) {
                    int n = g * 512 + u;
                    float s = bih1[n] + bhh1[n];
#pragma unroll
                    for (int ks = 0; ks < 8; ks++)
                        s += g_g1p[ks * 131072 + b * 2048 + n];
                    gt[g] = s;
                }
                float cn = sigf(gt[1]) * g_c1[gid] + sigf(gt[0]) * tanhf(gt[2]);
                g_c1[gid] = cn;
                h1n[gid] = sigf(gt[3]) * tanhf(cn);
            } else if (t > 0 && gid < 65536) {
                int idx = gid - 32768;
                float s = bcdn[idx & 511];
#pragma unroll
                for (int ks = 0; ks < 5; ks++) s += g_cdp[ks * 32768 + idx];
                g_cdn[idx] = fmaxf(s, 0.f);
            }
            if (t > 1) {
                for (int e = gid; e < Bsz * Vsz; e += GRID * NTHR) {
                    int m = e / Vsz, n = e - m * Vsz;
                    out[((long)m * Tsz + (t - 2)) * Vsz + n] =
                        g_lgp[0][m * 5120 + n] + g_lgp[1][m * 5120 + n]
                      + g_lgp[2][m * 5120 + n] + bcls[n];
                }
            }
            gsync(gs);
        }

        // ---- P3: LSTM2 (blk 0-95: 16nt x 6sk) || logits(t-1) units 0-51 ----
        if (bx < 96) {
            int ntile = bx / 6, ks = bx % 6;
            int kb, kl; l2_geom(ks, kb, kl);
            gemm2<2, 0>(h1n, h2o, nullptr, 0,
                        Wih2, 512, 512, Whh2, 512,
                        ntile * 128, 1 << 30, kb, kb + kl,
                        g_g2p + (long)ks * 131072, 2048, nullptr, nullptr, 0, sh);
        } else if (t > 0) {
            int u = bx - 96;               // 0..51
            int tile = u / 3, ks = u % 3;
            int kb, kl; lg_geom(ks, kb, kl);
            gemm2<0, 0>(g_cdn, nullptr, nullptr, 512,
                        emb, 512, 1 << 30, nullptr, 0,
                        tile * 128, Vsz, kb, kb + kl,
                        g_lgp[ks], 5120, nullptr, nullptr, 0, sh);
        }
        gsync(gs);

        // ---- P4: attention (blk 0-63) || logits(t-1) units 52-119 (64-131) ----
        if (bx < 64) {
            int b = bx, lane = tid & 31, w = tid >> 5;
            // cell2 (sums 6 split-K partials)
            {
                int u = tid;
                float gt[4];
#pragma unroll
                for (int g = 0; g < 4; g++) {
                    int n = g * 512 + u;
                    float s = bih2[n] + bhh2[n];
#pragma unroll
                    for (int ks = 0; ks < 6; ks++)
                        s += g_g2p[ks * 131072 + b * 2048 + n];
                    gt[g] = s;
                }
                float cn = sigf(gt[1]) * g_c2[b * 512 + u] + sigf(gt[0]) * tanhf(gt[2]);
                float h = sigf(gt[3]) * tanhf(cn);
                g_c2[b * 512 + u] = cn;
                h2n[b * 512 + u] = h;
                sh.u.a.h2s[u] = h;
            }
            __syncthreads();
            // q projection: 16 warps x 16 outputs (scale folded)
            {
                const float4* h24 = (const float4*)sh.u.a.h2s;
                float4 hv0 = h24[lane], hv1 = h24[32 + lane],
                       hv2 = h24[64 + lane], hv3 = h24[96 + lane];
#pragma unroll 2
                for (int jj = 0; jj < 16; jj++) {
                    int j = w * 16 + jj;
                    const float4* wr = (const float4*)(Wq + (long)j * 512);
                    float4 w0 = wr[lane], w1 = wr[32 + lane],
                           w2 = wr[64 + lane], w3 = wr[96 + lane];
                    float s = hv0.x * w0.x + hv0.y * w0.y + hv0.z * w0.z + hv0.w * w0.w
                            + hv1.x * w1.x + hv1.y * w1.y + hv1.z * w1.z + hv1.w * w1.w
                            + hv2.x * w2.x + hv2.y * w2.y + hv2.z * w2.z + hv2.w * w2.w
                            + hv3.x * w3.x + hv3.y * w3.y + hv3.z * w3.z + hv3.w * w3.w;
#pragma unroll
                    for (int o = 16; o; o >>= 1) s += __shfl_xor_sync(~0u, s, o);
                    if (lane == 0) sh.u.a.qs[j] = (s + bq[j]) * 0.0625f;
                }
            }
            __syncthreads();
            // scores: 16 warps x 64 rows, fp16 K via LDG.128
            {
                const float4* q4 = (const float4*)sh.u.a.qs;
                float4 qA = q4[2 * lane], qB = q4[2 * lane + 1];
                int rbase = w * 64;
#pragma unroll 4
                for (int i = 0; i < 64; i++) {
                    int row = rbase + i;
                    uint4 kv = *(const uint4*)(g_k + ((long)b * 1024 + row) * 256 + lane * 8);
                    float2 f0 = h2f(kv.x), f1 = h2f(kv.y),
                           f2 = h2f(kv.z), f3 = h2f(kv.w);
                    float a = qA.x * f0.x + qA.y * f0.y + qA.z * f1.x + qA.w * f1.y
                            + qB.x * f2.x + qB.y * f2.y + qB.z * f3.x + qB.w * f3.y;
#pragma unroll
                    for (int o = 16; o; o >>= 1) a += __shfl_xor_sync(~0u, a, o);
                    if (lane == 0) sh.u.a.sc[row] = a;
                }
            }
            __syncthreads();
            // softmax (block-local)
            float inv;
            {
                float* sc = sh.u.a.sc;
                float* red = sh.u.a.red;
                float mx = fmaxf(sc[tid], sc[tid + 512]);
#pragma unroll
                for (int o = 16; o; o >>= 1) mx = fmaxf(mx, __shfl_xor_sync(~0u, mx, o));
                if (lane == 0) red[w] = mx;
                __syncthreads();
                mx = red[0];
#pragma unroll
                for (int i = 1; i < 16; i++) mx = fmaxf(mx, red[i]);
                __syncthreads();
                float e0 = __expf(sc[tid] - mx);
                float e1 = __expf(sc[tid + 512] - mx);
                sc[tid] = e0; sc[tid + 512] = e1;
                float ls = e0 + e1;
#pragma unroll
                for (int o = 16; o; o >>= 1) ls += __shfl_xor_sync(~0u, ls, o);
                if (lane == 0) red[w] = ls;
                __syncthreads();
                float tot = 0.f;
#pragma unroll
                for (int i = 0; i < 16; i++) tot += red[i];
                inv = 1.f / tot;
            }
            // context: thread owns 8 cols (LDG.128 fp16), 8 s-strips via smem
            {
                const float* sc = sh.u.a.sc;
                int cg = tid & 63, sg = tid >> 6;
                const __half* vbase =
                    g_v + (long)b * (Ssz * Hsz) + (long)sg * 128 * 512 + cg * 8;
                float a0 = 0.f, a1 = 0.f, a2 = 0.f, a3 = 0.f;
                float a4 = 0.f, a5 = 0.f, a6 = 0.f, a7 = 0.f;
                const float* scp = sc + sg * 128;
#pragma unroll 8
                for (int s2 = 0; s2 < 128; s2++) {
                    uint4 vv = *(const uint4*)(vbase + (long)s2 * 512);
                    float wsc = scp[s2];
                    float2 f0 = h2f(vv.x), f1 = h2f(vv.y),
                           f2 = h2f(vv.z), f3 = h2f(vv.w);
                    a0 += wsc * f0.x; a1 += wsc * f0.y;
                    a2 += wsc * f1.x; a3 += wsc * f1.y;
                    a4 += wsc * f2.x; a5 += wsc * f2.y;
                    a6 += wsc * f3.x; a7 += wsc * f3.y;
                }
                float* pp = &sh.u.a.part[sg][cg * 8];
                *(float4*)pp       = make_float4(a0, a1, a2, a3);
                *(float4*)(pp + 4) = make_float4(a4, a5, a6, a7);
                __syncthreads();
                float s = 0.f;
#pragma unroll
                for (int g = 0; g < 8; g++) s += sh.u.a.part[g][tid];
                g_ctx[b * 512 + tid] = s * inv;
            }
        } else if (t > 0 && bx < 132) {
            int u = 52 + (bx - 64);        // 52..119
            int tile = u / 3, ks = u % 3;
            int kb, kl; lg_geom(ks, kb, kl);
            gemm2<0, 0>(g_cdn, nullptr, nullptr, 512,
                        emb, 512, 1 << 30, nullptr, 0,
                        tile * 128, Vsz, kb, kb + kl,
                        g_lgp[ks], 5120, nullptr, nullptr, 0, sh);
        }
        gsync(gs);
    }

    // ---- epilogue ----
    {
        const float* h2last = g_h2[Tsz & 1];
        // E1: cdn(Tsz-1) partials on 128-147 || logits-red(Tsz-2) on 0-127
        if (bx >= 128) {
            int u = bx - 128, ntile = u / 5, ks = u % 5;
            int kb = ks < 2 ? ks * 224 : 448 + (ks - 2) * 192;
            int kl = ks < 2 ? 224 : 192;
            gemm2<2, 0>(h2last, g_ctx, nullptr, 0,
                        Wcdn, 1024, 1 << 30, nullptr, 0,
                        ntile * 128, 1 << 30, kb, kb + kl,
                        g_cdp + (long)ks * 32768, 512, nullptr, nullptr, 0, sh);
        } else {
            int gid = bx * NTHR + tid;
            for (int e = gid; e < Bsz * Vsz; e += 128 * NTHR) {
                int m = e / Vsz, n = e - m * Vsz;
                out[((long)m * Tsz + (Tsz - 2)) * Vsz + n] =
                    g_lgp[0][m * 5120 + n] + g_lgp[1][m * 5120 + n]
                  + g_lgp[2][m * 5120 + n] + bcls[n];
            }
        }
        gsync(gs);
        // E2: cdn-reduce(Tsz-1)
        {
            int gid = bx * NTHR + tid;
            if (gid < 32768) {
                float s = bcdn[gid & 511];
#pragma unroll
                for (int ks = 0; ks < 5; ks++) s += g_cdp[ks * 32768 + gid];
                g_cdn[gid] = fmaxf(s, 0.f);
            }
        }
        gsync(gs);
        // E3: logits(Tsz-1), all 120 units on blocks 0-119
        if (bx < 120) {
            int tile = bx / 3, ks = bx % 3;
            int kb, kl; lg_geom(ks, kb, kl);
            gemm2<0, 0>(g_cdn, nullptr, nullptr, 512,
                        emb, 512, 1 << 30, nullptr, 0,
                        tile * 128, Vsz, kb, kb + kl,
                        g_lgp[ks], 5120, nullptr, nullptr, 0, sh);
        }
        gsync(gs);
        // E4: logits-reduce(Tsz-1)
        {
            int gid = bx * NTHR + tid;
            for (int e = gid; e < Bsz * Vsz; e += GRID * NTHR) {
                int m = e / Vsz, n = e - m * Vsz;
                out[((long)m * Tsz + (Tsz - 1)) * Vsz + n] =
                    g_lgp[0][m * 5120 + n] + g_lgp[1][m * 5120 + n]
                  + g_lgp[2][m * 5120 + n] + bcls[n];
            }
        }
    }
}

extern "C" void kernel_launch(void* const* d_in, const int* in_sizes, int n_in,
                              void* d_out, int out_size) {
    mega<<<GRID, NTHR>>>(
        (const float*)d_in[0],  (const int*)d_in[1],   (const float*)d_in[2],
        (const float*)d_in[3],  (const float*)d_in[4],
        (const float*)d_in[5],  (const float*)d_in[6],
        (const float*)d_in[7],  (const float*)d_in[8],
        (const float*)d_in[9],  (const float*)d_in[10],
        (const float*)d_in[11], (const float*)d_in[12],
        (const float*)d_in[13], (const float*)d_in[14],
        (const float*)d_in[15], (const float*)d_in[16],
        (const float*)d_in[17], (const float*)d_in[18],
        (const float*)d_in[19], (float*)d_out);
}

// round 13
// speedup vs baseline: 1.0482x; 1.0482x over previous
#include <cuda_runtime.h>
#include <cuda_fp16.h>

#define GRID 148
#define NTHR 512
#define Bsz 64
#define Ssz 1024
#define Tsz 300
#define Hsz 512
#define Vsz 5000
#define KQn 256

typedef unsigned long long ull;

// ---------------- device scratch ----------------
__device__ __half g_k[Bsz * Ssz * KQn];   // fp16 keys   (32 MB)
__device__ __half g_v[Bsz * Ssz * Hsz];   // fp16 values (64 MB)
__device__ float g_h1[2][Bsz * Hsz];
__device__ float g_c1[Bsz * Hsz];
__device__ float g_h2[2][Bsz * Hsz];
__device__ float g_c2[Bsz * Hsz];
__device__ float g_ctx[Bsz * Hsz];
__device__ float g_cdn[Bsz * Hsz];
__device__ float g_g1p[8 * Bsz * 2048];
__device__ float g_g2p[9 * Bsz * 2048];
__device__ float g_cdp[5 * Bsz * 512];
__device__ float g_lgp[2][Bsz * 5120];
__device__ volatile int g_flags[GRID];
__device__ volatile int g_genv;

// ---------------- shared arena (double-buffered GEMM tiles) ----------------
struct __align__(16) Sh {
    union {
        struct { float As[2][64][36]; float Bs[2][128][36]; } g;
        struct { float h2s[512]; float qs[256]; float sc[1024];
                 float red[16]; float part[8][528]; } a;
    } u;
    int toks[64];
};

// ---------------- grid barrier ----------------
__device__ __forceinline__ void gsync(int& gs) {
    gs++;
    __syncthreads();
    if (blockIdx.x == 0) {
        if (threadIdx.x > 0 && threadIdx.x < GRID)
            while (g_flags[threadIdx.x] < gs) __nanosleep(32);
        __syncthreads();
        if (threadIdx.x == 0) { __threadfence(); g_genv = gs; }
    } else if (threadIdx.x == 0) {
        __threadfence();
        g_flags[blockIdx.x] = gs;
        while (g_genv < gs) __nanosleep(32);
    }
    __syncthreads();
    __threadfence();
}

__device__ __forceinline__ float sigf(float x) { return 1.f / (1.f + __expf(-x)); }

__device__ __forceinline__ void fma2(ull& d, ull a, ull b) {
    asm("fma.rn.f32x2 %0, %1, %2, %3;" : "=l"(d) : "l"(a), "l"(b), "l"(d));
}
__device__ __forceinline__ float pairsum(ull x) {
    float lo, hi;
    asm("mov.b64 {%0, %1}, %2;" : "=f"(lo), "=f"(hi) : "l"(x));
    return lo + hi;
}
__device__ __forceinline__ float2 h2f(unsigned p) {
    __half2 h = *reinterpret_cast<__half2*>(&p);
    return __half22float2(h);
}

// ---------------- 64M x 128N GEMM tile, f32x2, double-buffered -------------
// out[m][n] = sum_k A[m][k] * B[n][k]
// Warp tile 8m x 2n (A broadcast loads; crossbar-balanced).
// AM 0: A row-major stride arow. AM 1: [emb[tok]|A1|A2] each 512.
// AM 2: [A0(512)|A1(512+)]. B row n: k<segB -> B0(len L0) else B1(len L1).
// OB 1: output cast to fp16.
template <int AM, int OB>
__device__ __forceinline__ void gemm2(
    const float* __restrict__ A0, const float* __restrict__ A1,
    const float* __restrict__ A2, long arow,
    const float* __restrict__ B0, long L0, int segB,
    const float* __restrict__ B1, long L1,
    int nbase, int Nmax, int kbeg, int kend,
    void* __restrict__ outp, long OS, const float* __restrict__ bias,
    const int* __restrict__ yy, int t, Sh& sh)
{
    const int tid = threadIdx.x;
    const int nt = tid & 31;
    const int w = tid >> 5;
    const int mw = (w & 7) * 8;          // warp m base (8 rows)
    const int nh = (w >> 3) * 64;        // warp n half (64 cols)
    const int ar = tid >> 3;             // fill row 0..63
    const int kq4 = (tid & 7) * 4;       // fill k col

    if (AM == 1) {
        if (tid < 64) sh.toks[tid] = (t == 0) ? 0 : yy[tid * Tsz + (t - 1)];
        __syncthreads();
    }

    ull acc[8][2];
#pragma unroll
    for (int i = 0; i < 8; i++) { acc[i][0] = 0ULL; acc[i][1] = 0ULL; }

    float4 pa, pb0, pb1;
    auto loadA = [&](int kb, float4& d) {
        int k = kb + kq4;
        const float* rp;
        if (AM == 0)      rp = A0 + (long)ar * arow + k;
        else if (AM == 1) rp = (k < 512)  ? A0 + (long)sh.toks[ar] * 512 + k
                         : (k < 1024) ? A1 + ar * 512 + (k - 512)
                                      : A2 + ar * 512 + (k - 1024);
        else              rp = (k < 512) ? A0 + ar * 512 + k
                                         : A1 + ar * 512 + (k - 512);
        d = *(const float4*)rp;
    };
    auto loadB = [&](int kb, int n, float4& d) {
        int ng = nbase + n;
        int k = kb + kq4;
        d = make_float4(0.f, 0.f, 0.f, 0.f);
        if (ng < Nmax) {
            const float* rp = (k < segB) ? B0 + (long)ng * L0 + k
                                         : B1 + (long)ng * L1 + (k - segB);
            d = *(const float4*)rp;
        }
    };

    // prologue: fill buffer 0 with slice 0
    loadA(kbeg, pa);
    loadB(kbeg, ar, pb0);
    loadB(kbeg, ar + 64, pb1);
    *(float4*)&sh.u.g.As[0][ar][kq4]      = pa;
    *(float4*)&sh.u.g.Bs[0][ar][kq4]      = pb0;
    *(float4*)&sh.u.g.Bs[0][ar + 64][kq4] = pb1;
    __syncthreads();

    const int nsl = (kend - kbeg) >> 5;
    for (int s = 0; s < nsl; s++) {
        const int cur = s & 1;
        const bool more = (s + 1 < nsl);
        if (more) {
            int kb = kbeg + ((s + 1) << 5);
            loadA(kb, pa);
            loadB(kb, ar, pb0);
            loadB(kb, ar + 64, pb1);
        }
#pragma unroll
        for (int kq = 0; kq < 8; kq++) {
            ulonglong2 b0 = *(const ulonglong2*)&sh.u.g.Bs[cur][nh + nt][4 * kq];
            ulonglong2 b1 = *(const ulonglong2*)&sh.u.g.Bs[cur][nh + nt + 32][4 * kq];
#pragma unroll
            for (int i = 0; i < 8; i++) {
                ulonglong2 a = *(const ulonglong2*)&sh.u.g.As[cur][mw + i][4 * kq];
                fma2(acc[i][0], a.x, b0.x);
                fma2(acc[i][0], a.y, b0.y);
                fma2(acc[i][1], a.x, b1.x);
                fma2(acc[i][1], a.y, b1.y);
            }
        }
        if (more) {
            const int nb_ = (s + 1) & 1;
            *(float4*)&sh.u.g.As[nb_][ar][kq4]      = pa;
            *(float4*)&sh.u.g.Bs[nb_][ar][kq4]      = pb0;
            *(float4*)&sh.u.g.Bs[nb_][ar + 64][kq4] = pb1;
        }
        __syncthreads();
    }

#pragma unroll
    for (int i = 0; i < 8; i++) {
        long m = mw + i;
#pragma unroll
        for (int j = 0; j < 2; j++) {
            int n = nbase + nh + nt + 32 * j;
            if (n < Nmax) {
                float s = pairsum(acc[i][j]);
                if (bias) s += bias[n];
                if (OB) ((__half*)outp)[m * OS + n] = __float2half(s);
                else    ((float*)outp)[m * OS + n] = s;
            }
        }
    }
}

// ---------------- persistent mega-kernel (round-11 schedule) ----------------
__global__ void __launch_bounds__(NTHR, 1)
mega(const float* __restrict__ enc, const int* __restrict__ y,
     const float* __restrict__ emb,
     const float* __restrict__ Wq, const float* __restrict__ bq,
     const float* __restrict__ Wk, const float* __restrict__ bk,
     const float* __restrict__ Wv, const float* __restrict__ bv,
     const float* __restrict__ Wih1, const float* __restrict__ bih1,
     const float* __restrict__ Whh1, const float* __restrict__ bhh1,
     const float* __restrict__ Wih2, const float* __restrict__ bih2,
     const float* __restrict__ Whh2, const float* __restrict__ bhh2,
     const float* __restrict__ Wcdn, const float* __restrict__ bcdn,
     const float* __restrict__ bcls, float* __restrict__ out)
{
    __shared__ Sh sh;
    const int tid = threadIdx.x;
    const int bx = blockIdx.x;
    int gs = g_genv;

    // ---- init: zero recurrent state ----
    for (int i = bx * NTHR + tid; i < 5 * Bsz * Hsz; i += GRID * NTHR) {
        int a = i >> 15, j = i & 32767;
        float* p = a == 0 ? g_h1[0] : a == 1 ? g_c1 : a == 2 ? g_h2[0]
                 : a == 3 ? g_c2 : g_ctx;
        p[j] = 0.f;
    }
    // ---- kv projection (fp16 output) ----
    for (int j = bx; j < 6144; j += GRID) {
        if (j < 2048) {
            int mt_ = j >> 1, nt_ = j & 1;
            gemm2<0, 1>(enc + (long)mt_ * 64 * 512, nullptr, nullptr, 512,
                        Wk, 512, 1 << 30, nullptr, 0,
                        nt_ * 128, 1 << 30, 0, 512,
                        g_k + (long)mt_ * 64 * KQn, KQn, bk, nullptr, 0, sh);
        } else {
            int v = j - 2048;
            int mt_ = v >> 2, nt_ = v & 3;
            gemm2<0, 1>(enc + (long)mt_ * 64 * 512, nullptr, nullptr, 512,
                        Wv, 512, 1 << 30, nullptr, 0,
                        nt_ * 128, 1 << 30, 0, 512,
                        g_v + (long)mt_ * 64 * Hsz, Hsz, bv, nullptr, 0, sh);
        }
    }
    gsync(gs);

    for (int t = 0; t < Tsz; t++) {
        const float* h1o = g_h1[t & 1];
        float*       h1n = g_h1[(t + 1) & 1];
        const float* h2o = g_h2[t & 1];
        float*       h2n = g_h2[(t + 1) & 1];

        // ---- P1: LSTM1 (blk 0-127: 16nt x 8sk, k=192) || cdn(t-1) (128-147) ----
        if (bx < 128) {
            int ntile = bx >> 3, ks = bx & 7;
            gemm2<1, 0>(emb, g_ctx, h1o, 0,
                        Wih1, 1024, 1024, Whh1, 512,
                        ntile * 128, 1 << 30, ks * 192, ks * 192 + 192,
                        g_g1p + (long)ks * 131072, 2048, nullptr, y, t, sh);
        } else if (t > 0) {
            int u = bx - 128, ntile = u / 5, ks = u % 5;
            int kb = ks < 2 ? ks * 224 : 448 + (ks - 2) * 192;
            int kl = ks < 2 ? 224 : 192;
            gemm2<2, 0>(h2o, g_ctx, nullptr, 0,
                        Wcdn, 1024, 1 << 30, nullptr, 0,
                        ntile * 128, 1 << 30, kb, kb + kl,
                        g_cdp + (long)ks * 32768, 512, nullptr, nullptr, 0, sh);
        }
        gsync(gs);

        // ---- P2: cell1 + cdn-red(t-1) + logits-red(t-2) ----
        {
            int gid = bx * NTHR + tid;
            if (gid < 32768) {
                int b = gid >> 9, u = gid & 511;
                float gt[4];
#pragma unroll
                for (int g = 0; g < 4; g++) {
                    int n = g * 512 + u;
                    float s = bih1[n] + bhh1[n];
#pragma unroll
                    for (int ks = 0; ks < 8; ks++)
                        s += g_g1p[ks * 131072 + b * 2048 + n];
                    gt[g] = s;
                }
                float cn = sigf(gt[1]) * g_c1[gid] + sigf(gt[0]) * tanhf(gt[2]);
                g_c1[gid] = cn;
                h1n[gid] = sigf(gt[3]) * tanhf(cn);
            } else if (t > 0 && gid < 65536) {
                int idx = gid - 32768;
                float s = bcdn[idx & 511];
#pragma unroll
                for (int ks = 0; ks < 5; ks++) s += g_cdp[ks * 32768 + idx];
                g_cdn[idx] = fmaxf(s, 0.f);
            }
            if (t > 1) {
                for (int e = gid; e < Bsz * Vsz; e += GRID * NTHR) {
                    int m = e / Vsz, n = e - m * Vsz;
                    out[((long)m * Tsz + (t - 2)) * Vsz + n] =
                        g_lgp[0][m * 5120 + n] + g_lgp[1][m * 5120 + n] + bcls[n];
                }
            }
            gsync(gs);
        }

        // ---- P3: LSTM2 (blk 0-143: 16nt x 9sk, uneven k) ----
        if (bx < 144) {
            int ntile = bx / 9, ks = bx % 9;
            int kb = ks < 5 ? ks * 128 : 640 + (ks - 5) * 96;
            int kl = ks < 5 ? 128 : 96;
            gemm2<2, 0>(h1n, h2o, nullptr, 0,
                        Wih2, 512, 512, Whh2, 512,
                        ntile * 128, 1 << 30, kb, kb + kl,
                        g_g2p + (long)ks * 131072, 2048, nullptr, nullptr, 0, sh);
        }
        gsync(gs);

        // ---- P4: attention (blk 0-63, block-local) || logits(t-1) (64-143) ----
        if (bx < 64) {
            int b = bx, lane = tid & 31, w = tid >> 5;
            // cell2 (sums 9 split-K partials)
            {
                int u = tid;
                float gt[4];
#pragma unroll
                for (int g = 0; g < 4; g++) {
                    int n = g * 512 + u;
                    float s = bih2[n] + bhh2[n];
#pragma unroll
                    for (int ks = 0; ks < 9; ks++)
                        s += g_g2p[ks * 131072 + b * 2048 + n];
                    gt[g] = s;
                }
                float cn = sigf(gt[1]) * g_c2[b * 512 + u] + sigf(gt[0]) * tanhf(gt[2]);
                float h = sigf(gt[3]) * tanhf(cn);
                g_c2[b * 512 + u] = cn;
                h2n[b * 512 + u] = h;
                sh.u.a.h2s[u] = h;
            }
            __syncthreads();
            // q projection: 16 warps x 16 outputs (scale folded)
            {
                const float4* h24 = (const float4*)sh.u.a.h2s;
                float4 hv0 = h24[lane], hv1 = h24[32 + lane],
                       hv2 = h24[64 + lane], hv3 = h24[96 + lane];
#pragma unroll 2
                for (int jj = 0; jj < 16; jj++) {
                    int j = w * 16 + jj;
                    const float4* wr = (const float4*)(Wq + (long)j * 512);
                    float4 w0 = wr[lane], w1 = wr[32 + lane],
                           w2 = wr[64 + lane], w3 = wr[96 + lane];
                    float s = hv0.x * w0.x + hv0.y * w0.y + hv0.z * w0.z + hv0.w * w0.w
                            + hv1.x * w1.x + hv1.y * w1.y + hv1.z * w1.z + hv1.w * w1.w
                            + hv2.x * w2.x + hv2.y * w2.y + hv2.z * w2.z + hv2.w * w2.w
                            + hv3.x * w3.x + hv3.y * w3.y + hv3.z * w3.z + hv3.w * w3.w;
#pragma unroll
                    for (int o = 16; o; o >>= 1) s += __shfl_xor_sync(~0u, s, o);
                    if (lane == 0) sh.u.a.qs[j] = (s + bq[j]) * 0.0625f;
                }
            }
            __syncthreads();
            // scores: 16 warps x 64 rows, fp16 K via LDG.128
            {
                const float4* q4 = (const float4*)sh.u.a.qs;
                float4 qA = q4[2 * lane], qB = q4[2 * lane + 1];
                int rbase = w * 64;
#pragma unroll 4
                for (int i = 0; i < 64; i++) {
                    int row = rbase + i;
                    uint4 kv = *(const uint4*)(g_k + ((long)b * 1024 + row) * 256 + lane * 8);
                    float2 f0 = h2f(kv.x), f1 = h2f(kv.y),
                           f2 = h2f(kv.z), f3 = h2f(kv.w);
                    float a = qA.x * f0.x + qA.y * f0.y + qA.z * f1.x + qA.w * f1.y
                            + qB.x * f2.x + qB.y * f2.y + qB.z * f3.x + qB.w * f3.y;
#pragma unroll
                    for (int o = 16; o; o >>= 1) a += __shfl_xor_sync(~0u, a, o);
                    if (lane == 0) sh.u.a.sc[row] = a;
                }
            }
            __syncthreads();
            // softmax (block-local)
            float inv;
            {
                float* sc = sh.u.a.sc;
                float* red = sh.u.a.red;
                float mx = fmaxf(sc[tid], sc[tid + 512]);
#pragma unroll
                for (int o = 16; o; o >>= 1) mx = fmaxf(mx, __shfl_xor_sync(~0u, mx, o));
                if (lane == 0) red[w] = mx;
                __syncthreads();
                mx = red[0];
#pragma unroll
                for (int i = 1; i < 16; i++) mx = fmaxf(mx, red[i]);
                __syncthreads();
                float e0 = __expf(sc[tid] - mx);
                float e1 = __expf(sc[tid + 512] - mx);
                sc[tid] = e0; sc[tid + 512] = e1;
                float ls = e0 + e1;
#pragma unroll
                for (int o = 16; o; o >>= 1) ls += __shfl_xor_sync(~0u, ls, o);
                if (lane == 0) red[w] = ls;
                __syncthreads();
                float tot = 0.f;
#pragma unroll
                for (int i = 0; i < 16; i++) tot += red[i];
                inv = 1.f / tot;
            }
            // context: thread owns 8 cols (LDG.128 fp16), 8 s-strips via smem
            {
                const float* sc = sh.u.a.sc;
                int cg = tid & 63, sg = tid >> 6;
                const __half* vbase =
                    g_v + (long)b * (Ssz * Hsz) + (long)sg * 128 * 512 + cg * 8;
                float a0 = 0.f, a1 = 0.f, a2 = 0.f, a3 = 0.f;
                float a4 = 0.f, a5 = 0.f, a6 = 0.f, a7 = 0.f;
                const float* scp = sc + sg * 128;
#pragma unroll 8
                for (int s2 = 0; s2 < 128; s2++) {
                    uint4 vv = *(const uint4*)(vbase + (long)s2 * 512);
                    float wsc = scp[s2];
                    float2 f0 = h2f(vv.x), f1 = h2f(vv.y),
                           f2 = h2f(vv.z), f3 = h2f(vv.w);
                    a0 += wsc * f0.x; a1 += wsc * f0.y;
                    a2 += wsc * f1.x; a3 += wsc * f1.y;
                    a4 += wsc * f2.x; a5 += wsc * f2.y;
                    a6 += wsc * f3.x; a7 += wsc * f3.y;
                }
                float* pp = &sh.u.a.part[sg][cg * 8];
                *(float4*)pp       = make_float4(a0, a1, a2, a3);
                *(float4*)(pp + 4) = make_float4(a4, a5, a6, a7);
                __syncthreads();
                float s = 0.f;
#pragma unroll
                for (int g = 0; g < 8; g++) s += sh.u.a.part[g][tid];
                g_ctx[b * 512 + tid] = s * inv;
            }
        } else if (t > 0 && bx < 144) {
            int u = bx - 64, tile = u >> 1, kh = u & 1;
            gemm2<0, 0>(g_cdn, nullptr, nullptr, 512,
                        emb, 512, 1 << 30, nullptr, 0,
                        tile * 128, Vsz, kh * 256, kh * 256 + 256,
                        g_lgp[kh], 5120, nullptr, nullptr, 0, sh);
        }
        gsync(gs);
    }

    // ---- epilogue ----
    {
        const float* h2last = g_h2[Tsz & 1];
        // E1: cdn(Tsz-1) partials on 128-147 || logits-red(Tsz-2) on 0-127
        if (bx >= 128) {
            int u = bx - 128, ntile = u / 5, ks = u % 5;
            int kb = ks < 2 ? ks * 224 : 448 + (ks - 2) * 192;
            int kl = ks < 2 ? 224 : 192;
            gemm2<2, 0>(h2last, g_ctx, nullptr, 0,
                        Wcdn, 1024, 1 << 30, nullptr, 0,
                        ntile * 128, 1 << 30, kb, kb + kl,
                        g_cdp + (long)ks * 32768, 512, nullptr, nullptr, 0, sh);
        } else {
            int gid = bx * NTHR + tid;
            for (int e = gid; e < Bsz * Vsz; e += 128 * NTHR) {
                int m = e / Vsz, n = e - m * Vsz;
                out[((long)m * Tsz + (Tsz - 2)) * Vsz + n] =
                    g_lgp[0][m * 5120 + n] + g_lgp[1][m * 5120 + n] + bcls[n];
            }
        }
        gsync(gs);
        // E2: cdn-reduce(Tsz-1)
        {
            int gid = bx * NTHR + tid;
            if (gid < 32768) {
                float s = bcdn[gid & 511];
#pragma unroll
                for (int ks = 0; ks < 5; ks++) s += g_cdp[ks * 32768 + gid];
                g_cdn[gid] = fmaxf(s, 0.f);
            }
        }
        gsync(gs);
        // E3: logits(Tsz-1) partials on 80 blocks
        if (bx < 80) {
            int tile = bx >> 1, kh = bx & 1;
            gemm2<0, 0>(g_cdn, nullptr, nullptr, 512,
                        emb, 512, 1 << 30, nullptr, 0,
                        tile * 128, Vsz, kh * 256, kh * 256 + 256,
                        g_lgp[kh], 5120, nullptr, nullptr, 0, sh);
        }
        gsync(gs);
        // E4: logits-reduce(Tsz-1)
        {
            int gid = bx * NTHR + tid;
            for (int e = gid; e < Bsz * Vsz; e += GRID * NTHR) {
                int m = e / Vsz, n = e - m * Vsz;
                out[((long)m * Tsz + (Tsz - 1)) * Vsz + n] =
                    g_lgp[0][m * 5120 + n] + g_lgp[1][m * 5120 + n] + bcls[n];
            }
        }
    }
}

extern "C" void kernel_launch(void* const* d_in, const int* in_sizes, int n_in,
                              void* d_out, int out_size) {
    mega<<<GRID, NTHR>>>(
        (const float*)d_in[0],  (const int*)d_in[1],   (const float*)d_in[2],
        (const float*)d_in[3],  (const float*)d_in[4],
        (const float*)d_in[5],  (const float*)d_in[6],
        (const float*)d_in[7],  (const float*)d_in[8],
        (const float*)d_in[9],  (const float*)d_in[10],
        (const float*)d_in[11], (const float*)d_in[12],
        (const float*)d_in[13], (const float*)d_in[14],
        (const float*)d_in[15], (const float*)d_in[16],
        (const float*)d_in[17], (const float*)d_in[18],
        (const float*)d_in[19], (float*)d_out);
}

// round 14
// speedup vs baseline: 1.0573x; 1.0087x over previous
#include <cuda_runtime.h>
#include <cuda_fp16.h>

#define GRID 148
#define NTHR 512
#define Bsz 64
#define Ssz 1024
#define Tsz 300
#define Hsz 512
#define Vsz 5000
#define KQn 256

typedef unsigned long long ull;

// ---------------- device scratch ----------------
__device__ __half g_k[Bsz * Ssz * KQn];   // fp16 keys   (32 MB)
__device__ __half g_v[Bsz * Ssz * Hsz];   // fp16 values (64 MB)
__device__ float g_h1[2][Bsz * Hsz];
__device__ float g_c1[Bsz * Hsz];
__device__ float g_h2[2][Bsz * Hsz];
__device__ float g_c2[Bsz * Hsz];
__device__ float g_ctx[Bsz * Hsz];
__device__ float g_cdn[Bsz * Hsz];
__device__ float g_g1p[8 * Bsz * 2048];
__device__ float g_g2p[9 * Bsz * 2048];
__device__ float g_cdp[5 * Bsz * 512];
__device__ float g_lgp[2][Bsz * 5120];
__device__ volatile int g_flags[GRID];
__device__ volatile int g_genv;

// ---------------- shared arena (double-buffered GEMM tiles) ----------------
struct __align__(16) Sh {
    union {
        struct { float As[2][64][36]; float Bs[2][128][36]; } g;
        struct { float h2s[512]; float qs[256]; float sc[1024];
                 float red[16]; float part[8][528]; } a;
    } u;
    int toks[64];
};

// ---------------- grid barrier ----------------
__device__ __forceinline__ void gsync(int& gs) {
    gs++;
    __syncthreads();
    if (blockIdx.x == 0) {
        if (threadIdx.x > 0 && threadIdx.x < GRID)
            while (g_flags[threadIdx.x] < gs) __nanosleep(32);
        __syncthreads();
        if (threadIdx.x == 0) { __threadfence(); g_genv = gs; }
    } else if (threadIdx.x == 0) {
        __threadfence();
        g_flags[blockIdx.x] = gs;
        while (g_genv < gs) __nanosleep(32);
    }
    __syncthreads();
    __threadfence();
}

__device__ __forceinline__ float sigf(float x) { return 1.f / (1.f + __expf(-x)); }

__device__ __forceinline__ void fma2(ull& d, ull a, ull b) {
    asm("fma.rn.f32x2 %0, %1, %2, %3;" : "=l"(d) : "l"(a), "l"(b), "l"(d));
}
__device__ __forceinline__ float pairsum(ull x) {
    float lo, hi;
    asm("mov.b64 {%0, %1}, %2;" : "=f"(lo), "=f"(hi) : "l"(x));
    return lo + hi;
}
__device__ __forceinline__ float2 h2f(unsigned p) {
    __half2 h = *reinterpret_cast<__half2*>(&p);
    return __half22float2(h);
}

// ---------------- 64M x 128N GEMM tile, f32x2, 4m x 4n, double-buffered ----
// out[m][n] = sum_k A[m][k] * B[n][k]
// AM 0: A row-major stride arow. AM 1: [emb[tok]|A1|A2] each 512.
// AM 2: [A0(512)|A1(512+)]. B row n: k<segB -> B0(len L0) else B1(len L1).
// OB 1: output cast to fp16.
template <int AM, int OB>
__device__ __forceinline__ void gemm2(
    const float* __restrict__ A0, const float* __restrict__ A1,
    const float* __restrict__ A2, long arow,
    const float* __restrict__ B0, long L0, int segB,
    const float* __restrict__ B1, long L1,
    int nbase, int Nmax, int kbeg, int kend,
    void* __restrict__ outp, long OS, const float* __restrict__ bias,
    const int* __restrict__ yy, int t, Sh& sh)
{
    const int tid = threadIdx.x;
    const int nt = tid & 31;             // lane -> n
    const int mt = tid >> 5;             // warp -> m group (uniform)
    const int ar = tid >> 3;             // fill row 0..63
    const int kq4 = (tid & 7) * 4;       // fill k col

    if (AM == 1) {
        if (tid < 64) sh.toks[tid] = (t == 0) ? 0 : yy[tid * Tsz + (t - 1)];
        __syncthreads();
    }

    ull acc[4][4];
#pragma unroll
    for (int i = 0; i < 4; i++)
#pragma unroll
        for (int j = 0; j < 4; j++) acc[i][j] = 0ULL;

    float4 pa, pb0, pb1;
    auto loadA = [&](int kb, float4& d) {
        int k = kb + kq4;
        const float* rp;
        if (AM == 0)      rp = A0 + (long)ar * arow + k;
        else if (AM == 1) rp = (k < 512)  ? A0 + (long)sh.toks[ar] * 512 + k
                         : (k < 1024) ? A1 + ar * 512 + (k - 512)
                                      : A2 + ar * 512 + (k - 1024);
        else              rp = (k < 512) ? A0 + ar * 512 + k
                                         : A1 + ar * 512 + (k - 512);
        d = *(const float4*)rp;
    };
    auto loadB = [&](int kb, int n, float4& d) {
        int ng = nbase + n;
        int k = kb + kq4;
        d = make_float4(0.f, 0.f, 0.f, 0.f);
        if (ng < Nmax) {
            const float* rp = (k < segB) ? B0 + (long)ng * L0 + k
                                         : B1 + (long)ng * L1 + (k - segB);
            d = *(const float4*)rp;
        }
    };

    // prologue: fill buffer 0 with slice 0
    loadA(kbeg, pa);
    loadB(kbeg, ar, pb0);
    loadB(kbeg, ar + 64, pb1);
    *(float4*)&sh.u.g.As[0][ar][kq4]      = pa;
    *(float4*)&sh.u.g.Bs[0][ar][kq4]      = pb0;
    *(float4*)&sh.u.g.Bs[0][ar + 64][kq4] = pb1;
    __syncthreads();

    const int nsl = (kend - kbeg) >> 5;
    for (int s = 0; s < nsl; s++) {
        const int cur = s & 1;
        const bool more = (s + 1 < nsl);
        if (more) {
            int kb = kbeg + ((s + 1) << 5);
            loadA(kb, pa);
            loadB(kb, ar, pb0);
            loadB(kb, ar + 64, pb1);
        }
#pragma unroll
        for (int kq = 0; kq < 8; kq++) {
            ull a0[4], a1[4], b0[4], b1[4];
#pragma unroll
            for (int j = 0; j < 4; j++) {
                ulonglong2 tb = *(const ulonglong2*)&sh.u.g.Bs[cur][nt + 32 * j][4 * kq];
                b0[j] = tb.x; b1[j] = tb.y;
            }
#pragma unroll
            for (int i = 0; i < 4; i++) {
                ulonglong2 ta = *(const ulonglong2*)&sh.u.g.As[cur][mt * 4 + i][4 * kq];
                a0[i] = ta.x; a1[i] = ta.y;
            }
#pragma unroll
            for (int i = 0; i < 4; i++)
#pragma unroll
                for (int j = 0; j < 4; j++) {
                    fma2(acc[i][j], a0[i], b0[j]);
                    fma2(acc[i][j], a1[i], b1[j]);
                }
        }
        if (more) {
            const int nb_ = (s + 1) & 1;
            *(float4*)&sh.u.g.As[nb_][ar][kq4]      = pa;
            *(float4*)&sh.u.g.Bs[nb_][ar][kq4]      = pb0;
            *(float4*)&sh.u.g.Bs[nb_][ar + 64][kq4] = pb1;
        }
        __syncthreads();
    }

#pragma unroll
    for (int i = 0; i < 4; i++) {
        long m = mt * 4 + i;
#pragma unroll
        for (int j = 0; j < 4; j++) {
            int n = nbase + nt + 32 * j;
            if (n < Nmax) {
                float s = pairsum(acc[i][j]);
                if (bias) s += bias[n];
                if (OB) ((__half*)outp)[m * OS + n] = __float2half(s);
                else    ((float*)outp)[m * OS + n] = s;
            }
        }
    }
}

// ---------------- persistent mega-kernel (round-11 schedule) ----------------
__global__ void __launch_bounds__(NTHR, 1)
mega(const float* __restrict__ enc, const int* __restrict__ y,
     const float* __restrict__ emb,
     const float* __restrict__ Wq, const float* __restrict__ bq,
     const float* __restrict__ Wk, const float* __restrict__ bk,
     const float* __restrict__ Wv, const float* __restrict__ bv,
     const float* __restrict__ Wih1, const float* __restrict__ bih1,
     const float* __restrict__ Whh1, const float* __restrict__ bhh1,
     const float* __restrict__ Wih2, const float* __restrict__ bih2,
     const float* __restrict__ Whh2, const float* __restrict__ bhh2,
     const float* __restrict__ Wcdn, const float* __restrict__ bcdn,
     const float* __restrict__ bcls, float* __restrict__ out)
{
    __shared__ Sh sh;
    const int tid = threadIdx.x;
    const int bx = blockIdx.x;
    int gs = g_genv;

    // ---- init: zero recurrent state ----
    for (int i = bx * NTHR + tid; i < 5 * Bsz * Hsz; i += GRID * NTHR) {
        int a = i >> 15, j = i & 32767;
        float* p = a == 0 ? g_h1[0] : a == 1 ? g_c1 : a == 2 ? g_h2[0]
                 : a == 3 ? g_c2 : g_ctx;
        p[j] = 0.f;
    }
    // ---- kv projection (fp16 output) ----
    for (int j = bx; j < 6144; j += GRID) {
        if (j < 2048) {
            int mt_ = j >> 1, nt_ = j & 1;
            gemm2<0, 1>(enc + (long)mt_ * 64 * 512, nullptr, nullptr, 512,
                        Wk, 512, 1 << 30, nullptr, 0,
                        nt_ * 128, 1 << 30, 0, 512,
                        g_k + (long)mt_ * 64 * KQn, KQn, bk, nullptr, 0, sh);
        } else {
            int v = j - 2048;
            int mt_ = v >> 2, nt_ = v & 3;
            gemm2<0, 1>(enc + (long)mt_ * 64 * 512, nullptr, nullptr, 512,
                        Wv, 512, 1 << 30, nullptr, 0,
                        nt_ * 128, 1 << 30, 0, 512,
                        g_v + (long)mt_ * 64 * Hsz, Hsz, bv, nullptr, 0, sh);
        }
    }
    gsync(gs);

    for (int t = 0; t < Tsz; t++) {
        const float* h1o = g_h1[t & 1];
        float*       h1n = g_h1[(t + 1) & 1];
        const float* h2o = g_h2[t & 1];
        float*       h2n = g_h2[(t + 1) & 1];

        // ---- P1: LSTM1 (blk 0-127: 16nt x 8sk, k=192) || cdn(t-1) (128-147) ----
        if (bx < 128) {
            int ntile = bx >> 3, ks = bx & 7;
            gemm2<1, 0>(emb, g_ctx, h1o, 0,
                        Wih1, 1024, 1024, Whh1, 512,
                        ntile * 128, 1 << 30, ks * 192, ks * 192 + 192,
                        g_g1p + (long)ks * 131072, 2048, nullptr, y, t, sh);
        } else if (t > 0) {
            int u = bx - 128, ntile = u / 5, ks = u % 5;
            int kb = ks < 2 ? ks * 224 : 448 + (ks - 2) * 192;
            int kl = ks < 2 ? 224 : 192;
            gemm2<2, 0>(h2o, g_ctx, nullptr, 0,
                        Wcdn, 1024, 1 << 30, nullptr, 0,
                        ntile * 128, 1 << 30, kb, kb + kl,
                        g_cdp + (long)ks * 32768, 512, nullptr, nullptr, 0, sh);
        }
        gsync(gs);

        // ---- P2: cell1 + cdn-red(t-1) + logits-red(t-2) ----
        {
            int gid = bx * NTHR + tid;
            if (gid < 32768) {
                int b = gid >> 9, u = gid & 511;
                float gt[4];
#pragma unroll
                for (int g = 0; g < 4; g++) {
                    int n = g * 512 + u;
                    float s = bih1[n] + bhh1[n];
#pragma unroll
                    for (int ks = 0; ks < 8; ks++)
                        s += g_g1p[ks * 131072 + b * 2048 + n];
                    gt[g] = s;
                }
                float cn = sigf(gt[1]) * g_c1[gid] + sigf(gt[0]) * tanhf(gt[2]);
                g_c1[gid] = cn;
                h1n[gid] = sigf(gt[3]) * tanhf(cn);
            } else if (t > 0 && gid < 65536) {
                int idx = gid - 32768;
                float s = bcdn[idx & 511];
#pragma unroll
                for (int ks = 0; ks < 5; ks++) s += g_cdp[ks * 32768 + idx];
                g_cdn[idx] = fmaxf(s, 0.f);
            }
            if (t > 1) {
                for (int e = gid; e < Bsz * Vsz; e += GRID * NTHR) {
                    int m = e / Vsz, n = e - m * Vsz;
                    out[((long)m * Tsz + (t - 2)) * Vsz + n] =
                        g_lgp[0][m * 5120 + n] + g_lgp[1][m * 5120 + n] + bcls[n];
                }
            }
            gsync(gs);
        }

        // ---- P3: LSTM2 (blk 0-143: 16nt x 9sk, uneven k) ----
        if (bx < 144) {
            int ntile = bx / 9, ks = bx % 9;
            int kb = ks < 5 ? ks * 128 : 640 + (ks - 5) * 96;
            int kl = ks < 5 ? 128 : 96;
            gemm2<2, 0>(h1n, h2o, nullptr, 0,
                        Wih2, 512, 512, Whh2, 512,
                        ntile * 128, 1 << 30, kb, kb + kl,
                        g_g2p + (long)ks * 131072, 2048, nullptr, nullptr, 0, sh);
        }
        gsync(gs);

        // ---- P4: attention (blk 0-63, block-local) || logits(t-1) (64-143) ----
        if (bx < 64) {
            int b = bx, lane = tid & 31, w = tid >> 5;
            // cell2 (sums 9 split-K partials)
            {
                int u = tid;
                float gt[4];
#pragma unroll
                for (int g = 0; g < 4; g++) {
                    int n = g * 512 + u;
                    float s = bih2[n] + bhh2[n];
#pragma unroll
                    for (int ks = 0; ks < 9; ks++)
                        s += g_g2p[ks * 131072 + b * 2048 + n];
                    gt[g] = s;
                }
                float cn = sigf(gt[1]) * g_c2[b * 512 + u] + sigf(gt[0]) * tanhf(gt[2]);
                float h = sigf(gt[3]) * tanhf(cn);
                g_c2[b * 512 + u] = cn;
                h2n[b * 512 + u] = h;
                sh.u.a.h2s[u] = h;
            }
            __syncthreads();
            // q projection: 16 warps x 16 outputs (scale folded)
            {
                const float4* h24 = (const float4*)sh.u.a.h2s;
                float4 hv0 = h24[lane], hv1 = h24[32 + lane],
                       hv2 = h24[64 + lane], hv3 = h24[96 + lane];
#pragma unroll 2
                for (int jj = 0; jj < 16; jj++) {
                    int j = w * 16 + jj;
                    const float4* wr = (const float4*)(Wq + (long)j * 512);
                    float4 w0 = wr[lane], w1 = wr[32 + lane],
                           w2 = wr[64 + lane], w3 = wr[96 + lane];
                    float s = hv0.x * w0.x + hv0.y * w0.y + hv0.z * w0.z + hv0.w * w0.w
                            + hv1.x * w1.x + hv1.y * w1.y + hv1.z * w1.z + hv1.w * w1.w
                            + hv2.x * w2.x + hv2.y * w2.y + hv2.z * w2.z + hv2.w * w2.w
                            + hv3.x * w3.x + hv3.y * w3.y + hv3.z * w3.z + hv3.w * w3.w;
#pragma unroll
                    for (int o = 16; o; o >>= 1) s += __shfl_xor_sync(~0u, s, o);
                    if (lane == 0) sh.u.a.qs[j] = (s + bq[j]) * 0.0625f;
                }
            }
            __syncthreads();
            // scores: 16 warps x 64 rows, fp16 K via LDG.128
            {
                const float4* q4 = (const float4*)sh.u.a.qs;
                float4 qA = q4[2 * lane], qB = q4[2 * lane + 1];
                int rbase = w * 64;
#pragma unroll 4
                for (int i = 0; i < 64; i++) {
                    int row = rbase + i;
                    uint4 kv = *(const uint4*)(g_k + ((long)b * 1024 + row) * 256 + lane * 8);
                    float2 f0 = h2f(kv.x), f1 = h2f(kv.y),
                           f2 = h2f(kv.z), f3 = h2f(kv.w);
                    float a = qA.x * f0.x + qA.y * f0.y + qA.z * f1.x + qA.w * f1.y
                            + qB.x * f2.x + qB.y * f2.y + qB.z * f3.x + qB.w * f3.y;
#pragma unroll
                    for (int o = 16; o; o >>= 1) a += __shfl_xor_sync(~0u, a, o);
                    if (lane == 0) sh.u.a.sc[row] = a;
                }
            }
            __syncthreads();
            // softmax (block-local)
            float inv;
            {
                float* sc = sh.u.a.sc;
                float* red = sh.u.a.red;
                float mx = fmaxf(sc[tid], sc[tid + 512]);
#pragma unroll
                for (int o = 16; o; o >>= 1) mx = fmaxf(mx, __shfl_xor_sync(~0u, mx, o));
                if (lane == 0) red[w] = mx;
                __syncthreads();
                mx = red[0];
#pragma unroll
                for (int i = 1; i < 16; i++) mx = fmaxf(mx, red[i]);
                __syncthreads();
                float e0 = __expf(sc[tid] - mx);
                float e1 = __expf(sc[tid + 512] - mx);
                sc[tid] = e0; sc[tid + 512] = e1;
                float ls = e0 + e1;
#pragma unroll
                for (int o = 16; o; o >>= 1) ls += __shfl_xor_sync(~0u, ls, o);
                if (lane == 0) red[w] = ls;
                __syncthreads();
                float tot = 0.f;
#pragma unroll
                for (int i = 0; i < 16; i++) tot += red[i];
                inv = 1.f / tot;
            }
            // context: thread owns 8 cols (LDG.128 fp16), 8 s-strips via smem
            {
                const float* sc = sh.u.a.sc;
                int cg = tid & 63, sg = tid >> 6;
                const __half* vbase =
                    g_v + (long)b * (Ssz * Hsz) + (long)sg * 128 * 512 + cg * 8;
                float a0 = 0.f, a1 = 0.f, a2 = 0.f, a3 = 0.f;
                float a4 = 0.f, a5 = 0.f, a6 = 0.f, a7 = 0.f;
                const float* scp = sc + sg * 128;
#pragma unroll 8
                for (int s2 = 0; s2 < 128; s2++) {
                    uint4 vv = *(const uint4*)(vbase + (long)s2 * 512);
                    float wsc = scp[s2];
                    float2 f0 = h2f(vv.x), f1 = h2f(vv.y),
                           f2 = h2f(vv.z), f3 = h2f(vv.w);
                    a0 += wsc * f0.x; a1 += wsc * f0.y;
                    a2 += wsc * f1.x; a3 += wsc * f1.y;
                    a4 += wsc * f2.x; a5 += wsc * f2.y;
                    a6 += wsc * f3.x; a7 += wsc * f3.y;
                }
                float* pp = &sh.u.a.part[sg][cg * 8];
                *(float4*)pp       = make_float4(a0, a1, a2, a3);
                *(float4*)(pp + 4) = make_float4(a4, a5, a6, a7);
                __syncthreads();
                float s = 0.f;
#pragma unroll
                for (int g = 0; g < 8; g++) s += sh.u.a.part[g][tid];
                g_ctx[b * 512 + tid] = s * inv;
            }
        } else if (t > 0 && bx < 144) {
            int u = bx - 64, tile = u >> 1, kh = u & 1;
            gemm2<0, 0>(g_cdn, nullptr, nullptr, 512,
                        emb, 512, 1 << 30, nullptr, 0,
                        tile * 128, Vsz, kh * 256, kh * 256 + 256,
                        g_lgp[kh], 5120, nullptr, nullptr, 0, sh);
        }
        gsync(gs);
    }

    // ---- epilogue ----
    {
        const float* h2last = g_h2[Tsz & 1];
        // E1: cdn(Tsz-1) partials on 128-147 || logits-red(Tsz-2) on 0-127
        if (bx >= 128) {
            int u = bx - 128, ntile = u / 5, ks = u % 5;
            int kb = ks < 2 ? ks * 224 : 448 + (ks - 2) * 192;
            int kl = ks < 2 ? 224 : 192;
            gemm2<2, 0>(h2last, g_ctx, nullptr, 0,
                        Wcdn, 1024, 1 << 30, nullptr, 0,
                        ntile * 128, 1 << 30, kb, kb + kl,
                        g_cdp + (long)ks * 32768, 512, nullptr, nullptr, 0, sh);
        } else {
            int gid = bx * NTHR + tid;
            for (int e = gid; e < Bsz * Vsz; e += 128 * NTHR) {
                int m = e / Vsz, n = e - m * Vsz;
                out[((long)m * Tsz + (Tsz - 2)) * Vsz + n] =
                    g_lgp[0][m * 5120 + n] + g_lgp[1][m * 5120 + n] + bcls[n];
            }
        }
        gsync(gs);
        // E2: cdn-reduce(Tsz-1)
        {
            int gid = bx * NTHR + tid;
            if (gid < 32768) {
                float s = bcdn[gid & 511];
#pragma unroll
                for (int ks = 0; ks < 5; ks++) s += g_cdp[ks * 32768 + gid];
                g_cdn[gid] = fmaxf(s, 0.f);
            }
        }
        gsync(gs);
        // E3: logits(Tsz-1) partials on 80 blocks
        if (bx < 80) {
            int tile = bx >> 1, kh = bx & 1;
            gemm2<0, 0>(g_cdn, nullptr, nullptr, 512,
                        emb, 512, 1 << 30, nullptr, 0,
                        tile * 128, Vsz, kh * 256, kh * 256 + 256,
                        g_lgp[kh], 5120, nullptr, nullptr, 0, sh);
        }
        gsync(gs);
        // E4: logits-reduce(Tsz-1)
        {
            int gid = bx * NTHR + tid;
            for (int e = gid; e < Bsz * Vsz; e += GRID * NTHR) {
                int m = e / Vsz, n = e - m * Vsz;
                out[((long)m * Tsz + (Tsz - 1)) * Vsz + n] =
                    g_lgp[0][m * 5120 + n] + g_lgp[1][m * 5120 + n] + bcls[n];
            }
        }
    }
}

extern "C" void kernel_launch(void* const* d_in, const int* in_sizes, int n_in,
                              void* d_out, int out_size) {
    mega<<<GRID, NTHR>>>(
        (const float*)d_in[0],  (const int*)d_in[1],   (const float*)d_in[2],
        (const float*)d_in[3],  (const float*)d_in[4],
        (const float*)d_in[5],  (const float*)d_in[6],
        (const float*)d_in[7],  (const float*)d_in[8],
        (const float*)d_in[9],  (const float*)d_in[10],
        (const float*)d_in[11], (const float*)d_in[12],
        (const float*)d_in[13], (const float*)d_in[14],
        (const float*)d_in[15], (const float*)d_in[16],
        (const float*)d_in[17], (const float*)d_in[18],
        (const float*)d_in[19], (float*)d_out);
}

// round 15
// speedup vs baseline: 1.1661x; 1.1029x over previous
#include <cuda_runtime.h>
#include <cuda_fp16.h>

#define GRID 148
#define NTHR 512
#define Bsz 64
#define Ssz 1024
#define Tsz 300
#define Hsz 512
#define Vsz 5000
#define KQn 256

typedef unsigned long long ull;

// ---------------- device scratch ----------------
__device__ __half g_k[Bsz * Ssz * KQn];   // fp16 keys
__device__ __half g_v[Bsz * Ssz * Hsz];   // fp16 values
__device__ __half g_wih1h[2048 * 1024];   // fp16 weight copies (gates only)
__device__ __half g_whh1h[2048 * 512];
__device__ __half g_wih2h[2048 * 512];
__device__ __half g_whh2h[2048 * 512];
__device__ float g_h1[2][Bsz * Hsz];
__device__ float g_c1[Bsz * Hsz];
__device__ float g_h2[2][Bsz * Hsz];
__device__ float g_c2[Bsz * Hsz];
__device__ float g_ctx[Bsz * Hsz];
__device__ float g_cdn[Bsz * Hsz];
__device__ float g_g1p[4 * Bsz * 2048];
__device__ float g_g2p[4 * Bsz * 2048];
__device__ float g_cdp[20 * Bsz * 512];
__device__ float g_lgp[2][Bsz * 5120];
__device__ volatile int g_flags[GRID];
__device__ volatile int g_genv;

// ---------------- shared arena ----------------
struct __align__(16) Sh {
    union {
        struct { float As[64][36]; float Bs[128][36]; } g;          // fp32 gemm
        struct { __half Ah[64][40]; __half Bh[128][40]; } th;       // tensor gemm
        struct { float h2s[512]; float qs[256]; float sc[1024];
                 float red[16]; float part[8][528]; } a;            // attention
    } u;
    int toks[64];
};

// ---------------- grid barrier ----------------
__device__ __forceinline__ void gsync(int& gs) {
    gs++;
    __syncthreads();
    if (blockIdx.x == 0) {
        if (threadIdx.x > 0 && threadIdx.x < GRID)
            while (g_flags[threadIdx.x] < gs) __nanosleep(32);
        __syncthreads();
        if (threadIdx.x == 0) { __threadfence(); g_genv = gs; }
    } else if (threadIdx.x == 0) {
        __threadfence();
        g_flags[blockIdx.x] = gs;
        while (g_genv < gs) __nanosleep(32);
    }
    __syncthreads();
    __threadfence();
}

__device__ __forceinline__ float sigf(float x) { return 1.f / (1.f + __expf(-x)); }

__device__ __forceinline__ void fma2(ull& d, ull a, ull b) {
    asm("fma.rn.f32x2 %0, %1, %2, %3;" : "=l"(d) : "l"(a), "l"(b), "l"(d));
}
__device__ __forceinline__ float pairsum(ull x) {
    float lo, hi;
    asm("mov.b64 {%0, %1}, %2;" : "=f"(lo), "=f"(hi) : "l"(x));
    return lo + hi;
}
__device__ __forceinline__ float2 h2f(unsigned p) {
    __half2 h = *reinterpret_cast<__half2*>(&p);
    return __half22float2(h);
}

// ---------------- tensor-core GEMM: 64M x 128N, HMMA m16n8k16 --------------
// out[m][n] = sum_k A[m][k] * B[n][k]; A fp32 (cvt to fp16), B fp16 weights.
// AM 1: A = [emb[tok]|A1|A2] each 512. AM 2: A = [A0(512)|A1(512+)].
// B row n: k<segB -> B0 (row len L0) else B1 (row len L1).
template <int AM>
__device__ __forceinline__ void gemmT(
    const float* __restrict__ A0, const float* __restrict__ A1,
    const float* __restrict__ A2,
    const __half* __restrict__ B0, long L0, int segB,
    const __half* __restrict__ B1, long L1,
    int nbase, int kbeg, int kend,
    float* __restrict__ outp, long OS,
    const int* __restrict__ yy, int t, Sh& sh)
{
    const int tid = threadIdx.x;
    const int lane = tid & 31, w = tid >> 5;
    const int mw = (w & 3) * 16;         // warp m base
    const int nw = (w >> 2) * 32;        // warp n base
    const int gr = lane >> 2;            // group row 0..7
    const int kc2 = (lane & 3) * 2;      // k/col pair base
    const int arow = tid >> 3;           // A fill row 0..63
    const int acol = (tid & 7) * 4;      // A fill halfs col
    const int brow = tid >> 2;           // B fill row 0..127
    const int bcol = (tid & 3) * 8;      // B fill halfs col

    if (AM == 1) {
        if (tid < 64) sh.toks[tid] = (t == 0) ? 0 : yy[tid * Tsz + (t - 1)];
        __syncthreads();
    }

    float acc[4][4];
#pragma unroll
    for (int j = 0; j < 4; j++)
#pragma unroll
        for (int i = 0; i < 4; i++) acc[j][i] = 0.f;

    for (int kb = kbeg; kb < kend; kb += 32) {
        // A fill: fp32 -> fp16 (64 x 32)
        {
            int k = kb + acol;
            const float* rp;
            if (AM == 1) rp = (k < 512)  ? A0 + (long)sh.toks[arow] * 512 + k
                           : (k < 1024) ? A1 + arow * 512 + (k - 512)
                                        : A2 + arow * 512 + (k - 1024);
            else         rp = (k < 512)  ? A0 + arow * 512 + k
                                         : A1 + arow * 512 + (k - 512);
            float4 v = *(const float4*)rp;
            __half2 p0 = __floats2half2_rn(v.x, v.y);
            __half2 p1 = __floats2half2_rn(v.z, v.w);
            *(uint2*)&sh.u.th.Ah[arow][acol] =
                make_uint2(*(unsigned*)&p0, *(unsigned*)&p1);
        }
        // B fill: fp16 copy (128 x 32)
        {
            int ng = nbase + brow;
            int k = kb + bcol;
            const __half* rp = (k < segB) ? B0 + (long)ng * L0 + k
                                          : B1 + (long)ng * L1 + (k - segB);
            *(uint4*)&sh.u.th.Bh[brow][bcol] = *(const uint4*)rp;
        }
        __syncthreads();
#pragma unroll
        for (int h = 0; h < 2; h++) {
            int k0 = h * 16;
            unsigned a0 = *(const unsigned*)&sh.u.th.Ah[mw + gr][k0 + kc2];
            unsigned a1 = *(const unsigned*)&sh.u.th.Ah[mw + 8 + gr][k0 + kc2];
            unsigned a2 = *(const unsigned*)&sh.u.th.Ah[mw + gr][k0 + kc2 + 8];
            unsigned a3 = *(const unsigned*)&sh.u.th.Ah[mw + 8 + gr][k0 + kc2 + 8];
#pragma unroll
            for (int j = 0; j < 4; j++) {
                int n = nw + j * 8 + gr;
                unsigned b0 = *(const unsigned*)&sh.u.th.Bh[n][k0 + kc2];
                unsigned b1 = *(const unsigned*)&sh.u.th.Bh[n][k0 + kc2 + 8];
                asm volatile(
                    "mma.sync.aligned.m16n8k16.row.col.f32.f16.f16.f32 "
                    "{%0,%1,%2,%3}, {%4,%5,%6,%7}, {%8,%9}, {%0,%1,%2,%3};"
                    : "+f"(acc[j][0]), "+f"(acc[j][1]),
                      "+f"(acc[j][2]), "+f"(acc[j][3])
                    : "r"(a0), "r"(a1), "r"(a2), "r"(a3), "r"(b0), "r"(b1));
            }
        }
        __syncthreads();
    }

#pragma unroll
    for (int j = 0; j < 4; j++) {
        int nn = nbase + nw + j * 8 + kc2;
        long m0 = mw + gr, m1 = mw + 8 + gr;
        *(float2*)&outp[m0 * OS + nn] = make_float2(acc[j][0], acc[j][1]);
        *(float2*)&outp[m1 * OS + nn] = make_float2(acc[j][2], acc[j][3]);
    }
}

// ---------------- fp32 f32x2 GEMM (R11 version, single-buffered) -----------
template <int AM, int OB>
__device__ __forceinline__ void gemm2(
    const float* __restrict__ A0, const float* __restrict__ A1,
    const float* __restrict__ A2, long arow,
    const float* __restrict__ B0, long L0, int segB,
    const float* __restrict__ B1, long L1,
    int nbase, int Nmax, int kbeg, int kend,
    void* __restrict__ outp, long OS, const float* __restrict__ bias,
    const int* __restrict__ yy, int t, Sh& sh)
{
    const int tid = threadIdx.x;
    const int nt = tid & 31;
    const int mt = tid >> 5;
    const int ar = tid >> 3;
    const int kq4 = (tid & 7) * 4;

    if (AM == 1) {
        if (tid < 64) sh.toks[tid] = (t == 0) ? 0 : yy[tid * Tsz + (t - 1)];
        __syncthreads();
    }

    ull acc[4][4];
#pragma unroll
    for (int i = 0; i < 4; i++)
#pragma unroll
        for (int j = 0; j < 4; j++) acc[i][j] = 0ULL;

    float4 pa, pb0, pb1;
    auto loadA = [&](int kb, float4& d) {
        int k = kb + kq4;
        const float* rp;
        if (AM == 0)      rp = A0 + (long)ar * arow + k;
        else if (AM == 1) rp = (k < 512)  ? A0 + (long)sh.toks[ar] * 512 + k
                         : (k < 1024) ? A1 + ar * 512 + (k - 512)
                                      : A2 + ar * 512 + (k - 1024);
        else              rp = (k < 512) ? A0 + ar * 512 + k
                                         : A1 + ar * 512 + (k - 512);
        d = *(const float4*)rp;
    };
    auto loadB = [&](int kb, int n, float4& d) {
        int ng = nbase + n;
        int k = kb + kq4;
        d = make_float4(0.f, 0.f, 0.f, 0.f);
        if (ng < Nmax) {
            const float* rp = (k < segB) ? B0 + (long)ng * L0 + k
                                         : B1 + (long)ng * L1 + (k - segB);
            d = *(const float4*)rp;
        }
    };

    loadA(kbeg, pa);
    loadB(kbeg, ar, pb0);
    loadB(kbeg, ar + 64, pb1);

    for (int kb = kbeg; kb < kend; kb += 32) {
        __syncthreads();
        *(float4*)&sh.u.g.As[ar][kq4]      = pa;
        *(float4*)&sh.u.g.Bs[ar][kq4]      = pb0;
        *(float4*)&sh.u.g.Bs[ar + 64][kq4] = pb1;
        __syncthreads();
        if (kb + 32 < kend) {
            loadA(kb + 32, pa);
            loadB(kb + 32, ar, pb0);
            loadB(kb + 32, ar + 64, pb1);
        }
#pragma unroll
        for (int kq = 0; kq < 8; kq++) {
            ull a0[4], a1[4], b0[4], b1[4];
#pragma unroll
            for (int j = 0; j < 4; j++) {
                ulonglong2 tb = *(const ulonglong2*)&sh.u.g.Bs[nt + 32 * j][4 * kq];
                b0[j] = tb.x; b1[j] = tb.y;
            }
#pragma unroll
            for (int i = 0; i < 4; i++) {
                ulonglong2 ta = *(const ulonglong2*)&sh.u.g.As[mt * 4 + i][4 * kq];
                a0[i] = ta.x; a1[i] = ta.y;
            }
#pragma unroll
            for (int i = 0; i < 4; i++)
#pragma unroll
                for (int j = 0; j < 4; j++) {
                    fma2(acc[i][j], a0[i], b0[j]);
                    fma2(acc[i][j], a1[i], b1[j]);
                }
        }
    }
    __syncthreads();

#pragma unroll
    for (int i = 0; i < 4; i++) {
        long m = mt * 4 + i;
#pragma unroll
        for (int j = 0; j < 4; j++) {
            int n = nbase + nt + 32 * j;
            if (n < Nmax) {
                float s = pairsum(acc[i][j]);
                if (bias) s += bias[n];
                if (OB) ((__half*)outp)[m * OS + n] = __float2half(s);
                else    ((float*)outp)[m * OS + n] = s;
            }
        }
    }
}

// cdn split-K geometry: 20 chunks {64x12, 32x8} over k=1024
__device__ __forceinline__ void cd_geom(int ks, int& kb, int& kl) {
    if (ks < 12) { kb = ks * 64; kl = 64; }
    else         { kb = 768 + (ks - 12) * 32; kl = 32; }
}

// ---------------- persistent mega-kernel ----------------
__global__ void __launch_bounds__(NTHR, 1)
mega(const float* __restrict__ enc, const int* __restrict__ y,
     const float* __restrict__ emb,
     const float* __restrict__ Wq, const float* __restrict__ bq,
     const float* __restrict__ Wk, const float* __restrict__ bk,
     const float* __restrict__ Wv, const float* __restrict__ bv,
     const float* __restrict__ Wih1, const float* __restrict__ bih1,
     const float* __restrict__ Whh1, const float* __restrict__ bhh1,
     const float* __restrict__ Wih2, const float* __restrict__ bih2,
     const float* __restrict__ Whh2, const float* __restrict__ bhh2,
     const float* __restrict__ Wcdn, const float* __restrict__ bcdn,
     const float* __restrict__ bcls, float* __restrict__ out)
{
    __shared__ Sh sh;
    const int tid = threadIdx.x;
    const int bx = blockIdx.x;
    int gs = g_genv;

    // ---- init: zero state + fp16 weight conversion ----
    {
        int gid = bx * NTHR + tid;
        for (int i = gid; i < 5 * Bsz * Hsz; i += GRID * NTHR) {
            int a = i >> 15, j = i & 32767;
            float* p = a == 0 ? g_h1[0] : a == 1 ? g_c1 : a == 2 ? g_h2[0]
                     : a == 3 ? g_c2 : g_ctx;
            p[j] = 0.f;
        }
        for (int i = gid; i < 2048 * 1024; i += GRID * NTHR)
            g_wih1h[i] = __float2half(Wih1[i]);
        for (int i = gid; i < 2048 * 512; i += GRID * NTHR) {
            g_whh1h[i] = __float2half(Whh1[i]);
            g_wih2h[i] = __float2half(Wih2[i]);
            g_whh2h[i] = __float2half(Whh2[i]);
        }
    }
    // ---- kv projection (fp16 output, fp32 gemm) ----
    for (int j = bx; j < 6144; j += GRID) {
        if (j < 2048) {
            int mt_ = j >> 1, nt_ = j & 1;
            gemm2<0, 1>(enc + (long)mt_ * 64 * 512, nullptr, nullptr, 512,
                        Wk, 512, 1 << 30, nullptr, 0,
                        nt_ * 128, 1 << 30, 0, 512,
                        g_k + (long)mt_ * 64 * KQn, KQn, bk, nullptr, 0, sh);
        } else {
            int v = j - 2048;
            int mt_ = v >> 2, nt_ = v & 3;
            gemm2<0, 1>(enc + (long)mt_ * 64 * 512, nullptr, nullptr, 512,
                        Wv, 512, 1 << 30, nullptr, 0,
                        nt_ * 128, 1 << 30, 0, 512,
                        g_v + (long)mt_ * 64 * Hsz, Hsz, bv, nullptr, 0, sh);
        }
    }
    gsync(gs);

    for (int t = 0; t < Tsz; t++) {
        const float* h1o = g_h1[t & 1];
        float*       h1n = g_h1[(t + 1) & 1];
        const float* h2o = g_h2[t & 1];
        float*       h2n = g_h2[(t + 1) & 1];

        // ---- P1: LSTM1 tensor (blk 0-63: 16nt x 4sk, k=384)
        //          || cdn(t-1) fp32 (blk 64-143: 4nt x 20sk) ----
        if (bx < 64) {
            int ntile = bx >> 2, ks = bx & 3;
            gemmT<1>(emb, g_ctx, h1o,
                     g_wih1h, 1024, 1024, g_whh1h, 512,
                     ntile * 128, ks * 384, ks * 384 + 384,
                     g_g1p + (long)ks * 131072, 2048, y, t, sh);
        } else if (t > 0 && bx < 144) {
            int u = bx - 64, ntile = u / 20, ks = u % 20;
            int kb, kl; cd_geom(ks, kb, kl);
            gemm2<2, 0>(h2o, g_ctx, nullptr, 0,
                        Wcdn, 1024, 1 << 30, nullptr, 0,
                        ntile * 128, 1 << 30, kb, kb + kl,
                        g_cdp + (long)ks * 32768, 512, nullptr, nullptr, 0, sh);
        }
        gsync(gs);

        // ---- P2: cell1 + cdn-red(t-1) + logits-red(t-2) ----
        {
            int gid = bx * NTHR + tid;
            if (gid < 32768) {
                int b = gid >> 9, u = gid & 511;
                float gt[4];
#pragma unroll
                for (int g = 0; g < 4; g++) {
                    int n = g * 512 + u;
                    float s = bih1[n] + bhh1[n];
#pragma unroll
                    for (int ks = 0; ks < 4; ks++)
                        s += g_g1p[ks * 131072 + b * 2048 + n];
                    gt[g] = s;
                }
                float cn = sigf(gt[1]) * g_c1[gid] + sigf(gt[0]) * tanhf(gt[2]);
                g_c1[gid] = cn;
                h1n[gid] = sigf(gt[3]) * tanhf(cn);
            } else if (t > 0 && gid < 65536) {
                int idx = gid - 32768;
                float s = bcdn[idx & 511];
#pragma unroll
                for (int ks = 0; ks < 20; ks++) s += g_cdp[ks * 32768 + idx];
                g_cdn[idx] = fmaxf(s, 0.f);
            }
            if (t > 1) {
                for (int e = gid; e < Bsz * Vsz; e += GRID * NTHR) {
                    int m = e / Vsz, n = e - m * Vsz;
                    out[((long)m * Tsz + (t - 2)) * Vsz + n] =
                        g_lgp[0][m * 5120 + n] + g_lgp[1][m * 5120 + n] + bcls[n];
                }
            }
            gsync(gs);
        }

        // ---- P3: LSTM2 tensor (blk 0-63: 16nt x 4sk, k=256) ----
        if (bx < 64) {
            int ntile = bx >> 2, ks = bx & 3;
            gemmT<2>(h1n, h2o, nullptr,
                     g_wih2h, 512, 512, g_whh2h, 512,
                     ntile * 128, ks * 256, ks * 256 + 256,
                     g_g2p + (long)ks * 131072, 2048, nullptr, 0, sh);
        }
        gsync(gs);

        // ---- P4: attention (blk 0-63) || logits(t-1) fp32 (blk 64-143) ----
        if (bx < 64) {
            int b = bx, lane = tid & 31, w = tid >> 5;
            // cell2 (4 split-K partials)
            {
                int u = tid;
                float gt[4];
#pragma unroll
                for (int g = 0; g < 4; g++) {
                    int n = g * 512 + u;
                    float s = bih2[n] + bhh2[n];
#pragma unroll
                    for (int ks = 0; ks < 4; ks++)
                        s += g_g2p[ks * 131072 + b * 2048 + n];
                    gt[g] = s;
                }
                float cn = sigf(gt[1]) * g_c2[b * 512 + u] + sigf(gt[0]) * tanhf(gt[2]);
                float h = sigf(gt[3]) * tanhf(cn);
                g_c2[b * 512 + u] = cn;
                h2n[b * 512 + u] = h;
                sh.u.a.h2s[u] = h;
            }
            __syncthreads();
            // q projection
            {
                const float4* h24 = (const float4*)sh.u.a.h2s;
                float4 hv0 = h24[lane], hv1 = h24[32 + lane],
                       hv2 = h24[64 + lane], hv3 = h24[96 + lane];
#pragma unroll 2
                for (int jj = 0; jj < 16; jj++) {
                    int j = w * 16 + jj;
                    const float4* wr = (const float4*)(Wq + (long)j * 512);
                    float4 w0 = wr[lane], w1 = wr[32 + lane],
                           w2 = wr[64 + lane], w3 = wr[96 + lane];
                    float s = hv0.x * w0.x + hv0.y * w0.y + hv0.z * w0.z + hv0.w * w0.w
                            + hv1.x * w1.x + hv1.y * w1.y + hv1.z * w1.z + hv1.w * w1.w
                            + hv2.x * w2.x + hv2.y * w2.y + hv2.z * w2.z + hv2.w * w2.w
                            + hv3.x * w3.x + hv3.y * w3.y + hv3.z * w3.z + hv3.w * w3.w;
#pragma unroll
                    for (int o = 16; o; o >>= 1) s += __shfl_xor_sync(~0u, s, o);
                    if (lane == 0) sh.u.a.qs[j] = (s + bq[j]) * 0.0625f;
                }
            }
            __syncthreads();
            // scores: fp16 K via LDG.128
            {
                const float4* q4 = (const float4*)sh.u.a.qs;
                float4 qA = q4[2 * lane], qB = q4[2 * lane + 1];
                int rbase = w * 64;
#pragma unroll 4
                for (int i = 0; i < 64; i++) {
                    int row = rbase + i;
                    uint4 kv = *(const uint4*)(g_k + ((long)b * 1024 + row) * 256 + lane * 8);
                    float2 f0 = h2f(kv.x), f1 = h2f(kv.y),
                           f2 = h2f(kv.z), f3 = h2f(kv.w);
                    float a = qA.x * f0.x + qA.y * f0.y + qA.z * f1.x + qA.w * f1.y
                            + qB.x * f2.x + qB.y * f2.y + qB.z * f3.x + qB.w * f3.y;
#pragma unroll
                    for (int o = 16; o; o >>= 1) a += __shfl_xor_sync(~0u, a, o);
                    if (lane == 0) sh.u.a.sc[row] = a;
                }
            }
            __syncthreads();
            // softmax
            float inv;
            {
                float* sc = sh.u.a.sc;
                float* red = sh.u.a.red;
                float mx = fmaxf(sc[tid], sc[tid + 512]);
#pragma unroll
                for (int o = 16; o; o >>= 1) mx = fmaxf(mx, __shfl_xor_sync(~0u, mx, o));
                if (lane == 0) red[w] = mx;
                __syncthreads();
                mx = red[0];
#pragma unroll
                for (int i = 1; i < 16; i++) mx = fmaxf(mx, red[i]);
                __syncthreads();
                float e0 = __expf(sc[tid] - mx);
                float e1 = __expf(sc[tid + 512] - mx);
                sc[tid] = e0; sc[tid + 512] = e1;
                float ls = e0 + e1;
#pragma unroll
                for (int o = 16; o; o >>= 1) ls += __shfl_xor_sync(~0u, ls, o);
                if (lane == 0) red[w] = ls;
                __syncthreads();
                float tot = 0.f;
#pragma unroll
                for (int i = 0; i < 16; i++) tot += red[i];
                inv = 1.f / tot;
            }
            // context
            {
                const float* sc = sh.u.a.sc;
                int cg = tid & 63, sg = tid >> 6;
                const __half* vbase =
                    g_v + (long)b * (Ssz * Hsz) + (long)sg * 128 * 512 + cg * 8;
                float a0 = 0.f, a1 = 0.f, a2 = 0.f, a3 = 0.f;
                float a4 = 0.f, a5 = 0.f, a6 = 0.f, a7 = 0.f;
                const float* scp = sc + sg * 128;
#pragma unroll 8
                for (int s2 = 0; s2 < 128; s2++) {
                    uint4 vv = *(const uint4*)(vbase + (long)s2 * 512);
                    float wsc = scp[s2];
                    float2 f0 = h2f(vv.x), f1 = h2f(vv.y),
                           f2 = h2f(vv.z), f3 = h2f(vv.w);
                    a0 += wsc * f0.x; a1 += wsc * f0.y;
                    a2 += wsc * f1.x; a3 += wsc * f1.y;
                    a4 += wsc * f2.x; a5 += wsc * f2.y;
                    a6 += wsc * f3.x; a7 += wsc * f3.y;
                }
                float* pp = &sh.u.a.part[sg][cg * 8];
                *(float4*)pp       = make_float4(a0, a1, a2, a3);
                *(float4*)(pp + 4) = make_float4(a4, a5, a6, a7);
                __syncthreads();
                float s = 0.f;
#pragma unroll
                for (int g = 0; g < 8; g++) s += sh.u.a.part[g][tid];
                g_ctx[b * 512 + tid] = s * inv;
            }
        } else if (t > 0 && bx < 144) {
            int u = bx - 64, tile = u >> 1, kh = u & 1;
            gemm2<0, 0>(g_cdn, nullptr, nullptr, 512,
                        emb, 512, 1 << 30, nullptr, 0,
                        tile * 128, Vsz, kh * 256, kh * 256 + 256,
                        g_lgp[kh], 5120, nullptr, nullptr, 0, sh);
        }
        gsync(gs);
    }

    // ---- epilogue ----
    {
        const float* h2last = g_h2[Tsz & 1];
        // E1: cdn(Tsz-1) partials (blk 0-79) || logits-red(Tsz-2) (blk 80-147)
        if (bx < 80) {
            int ntile = bx / 20, ks = bx % 20;
            int kb, kl; cd_geom(ks, kb, kl);
            gemm2<2, 0>(h2last, g_ctx, nullptr, 0,
                        Wcdn, 1024, 1 << 30, nullptr, 0,
                        ntile * 128, 1 << 30, kb, kb + kl,
                        g_cdp + (long)ks * 32768, 512, nullptr, nullptr, 0, sh);
        } else {
            int gid = (bx - 80) * NTHR + tid;
            for (int e = gid; e < Bsz * Vsz; e += 68 * NTHR) {
                int m = e / Vsz, n = e - m * Vsz;
                out[((long)m * Tsz + (Tsz - 2)) * Vsz + n] =
                    g_lgp[0][m * 5120 + n] + g_lgp[1][m * 5120 + n] + bcls[n];
            }
        }
        gsync(gs);
        // E2: cdn-reduce(Tsz-1)
        {
            int gid = bx * NTHR + tid;
            if (gid < 32768) {
                float s = bcdn[gid & 511];
#pragma unroll
                for (int ks = 0; ks < 20; ks++) s += g_cdp[ks * 32768 + gid];
                g_cdn[gid] = fmaxf(s, 0.f);
            }
        }
        gsync(gs);
        // E3: logits(Tsz-1) partials on 80 blocks
        if (bx < 80) {
            int tile = bx >> 1, kh = bx & 1;
            gemm2<0, 0>(g_cdn, nullptr, nullptr, 512,
                        emb, 512, 1 << 30, nullptr, 0,
                        tile * 128, Vsz, kh * 256, kh * 256 + 256,
                        g_lgp[kh], 5120, nullptr, nullptr, 0, sh);
        }
        gsync(gs);
        // E4: logits-reduce(Tsz-1)
        {
            int gid = bx * NTHR + tid;
            for (int e = gid; e < Bsz * Vsz; e += GRID * NTHR) {
                int m = e / Vsz, n = e - m * Vsz;
                out[((long)m * Tsz + (Tsz - 1)) * Vsz + n] =
                    g_lgp[0][m * 5120 + n] + g_lgp[1][m * 5120 + n] + bcls[n];
            }
        }
    }
}

extern "C" void kernel_launch(void* const* d_in, const int* in_sizes, int n_in,
                              void* d_out, int out_size) {
    mega<<<GRID, NTHR>>>(
        (const float*)d_in[0],  (const int*)d_in[1],   (const float*)d_in[2],
        (const float*)d_in[3],  (const float*)d_in[4],
        (const float*)d_in[5],  (const float*)d_in[6],
        (const float*)d_in[7],  (const float*)d_in[8],
        (const float*)d_in[9],  (const float*)d_in[10],
        (const float*)d_in[11], (const float*)d_in[12],
        (const float*)d_in[13], (const float*)d_in[14],
        (const float*)d_in[15], (const float*)d_in[16],
        (const float*)d_in[17], (const float*)d_in[18],
        (const float*)d_in[19], (float*)d_out);
}